// round 7
// baseline (speedup 1.0000x reference)
#include <cuda_runtime.h>
#include <math.h>

// ---------------- problem constants ----------------
#define Bb 8
#define LL_ 1024
#define EE 512
#define HH 8
#define HD 64
#define FFD 2048
#define DEPTH_ 4
#define MM (Bb*LL_)   // 8192

// ---------------- device scratch (no allocations allowed) ----------------
__device__ float g_x   [(size_t)MM * EE];          // 16 MB  activations
__device__ float g_qkv [(size_t)MM * 3 * EE];      // 48 MB
__device__ float g_log [(size_t)Bb * HH * LL_ * LL_]; // 256 MB per-head logits
__device__ float g_W   [(size_t)Bb * LL_ * LL_];   // 32 MB  attention weights
__device__ float g_sa  [(size_t)MM * EE];          // 16 MB  attn out / ffn out
__device__ float g_h   [(size_t)MM * FFD];         // 64 MB  ffn hidden

// ---------------- generic SGEMM: C[M,N] = A[M,K] @ op(B) + bias ----------------
// BT=true : B is [N,K] row-major (weights, K contiguous)
// BT=false: B is [K,N] row-major (N contiguous)
// z-batch: zi = z % zmod, zo = z / zmod; ptr += zi*zs + zo*zs2
#define BM 128
#define BN 128
#define BK 8
#define TM 8
#define TN 8

template<bool BT, bool RELU>
__global__ void __launch_bounds__(256)
sgemm_kernel(const float* __restrict__ A, int lda, long long zsa, long long zsa2,
             const float* __restrict__ Bm, int ldb, long long zsb, long long zsb2,
             float* __restrict__ C, int ldc, long long zsc, long long zsc2,
             const float* __restrict__ bias,
             int M, int N, int K, int zmod)
{
    int z  = blockIdx.z;
    int zi = z % zmod;
    int zo = z / zmod;
    A  += (long long)zi * zsa + (long long)zo * zsa2;
    Bm += (long long)zi * zsb + (long long)zo * zsb2;
    C  += (long long)zi * zsc + (long long)zo * zsc2;

    __shared__ float As[BK][BM];
    __shared__ float Bs[BK][BN];

    const int tid = threadIdx.x;
    const int tx  = tid & 15;
    const int ty  = tid >> 4;
    const int m0  = blockIdx.y * BM;
    const int n0  = blockIdx.x * BN;

    const int arow = tid >> 1;        // 0..127
    const int acol = (tid & 1) * 4;   // 0 or 4

    float acc[TM][TN];
    #pragma unroll
    for (int i = 0; i < TM; i++)
        #pragma unroll
        for (int j = 0; j < TN; j++) acc[i][j] = 0.f;

    for (int k0 = 0; k0 < K; k0 += BK) {
        // A tile [BM x BK], K-contiguous, store transposed
        float4 av = *reinterpret_cast<const float4*>(
            &A[(long long)(m0 + arow) * lda + (k0 + acol)]);
        As[acol + 0][arow] = av.x;
        As[acol + 1][arow] = av.y;
        As[acol + 2][arow] = av.z;
        As[acol + 3][arow] = av.w;

        if (BT) {
            float4 bv = *reinterpret_cast<const float4*>(
                &Bm[(long long)(n0 + arow) * ldb + (k0 + acol)]);
            Bs[acol + 0][arow] = bv.x;
            Bs[acol + 1][arow] = bv.y;
            Bs[acol + 2][arow] = bv.z;
            Bs[acol + 3][arow] = bv.w;
        } else {
            int brow = tid >> 5;            // 0..7
            int bcol = (tid & 31) * 4;      // 0..124
            float4 bv = *reinterpret_cast<const float4*>(
                &Bm[(long long)(k0 + brow) * ldb + (n0 + bcol)]);
            *reinterpret_cast<float4*>(&Bs[brow][bcol]) = bv;
        }
        __syncthreads();

        #pragma unroll
        for (int kk = 0; kk < BK; kk++) {
            float af[TM], bf[TN];
            #pragma unroll
            for (int i = 0; i < TM; i++) af[i] = As[kk][ty * TM + i];
            #pragma unroll
            for (int j = 0; j < TN; j++) bf[j] = Bs[kk][tx * TN + j];
            #pragma unroll
            for (int i = 0; i < TM; i++)
                #pragma unroll
                for (int j = 0; j < TN; j++)
                    acc[i][j] += af[i] * bf[j];
        }
        __syncthreads();
    }

    #pragma unroll
    for (int i = 0; i < TM; i++) {
        int m = m0 + ty * TM + i;
        #pragma unroll
        for (int jj = 0; jj < TN; jj += 4) {
            float4 o;
            float* po = &o.x;
            #pragma unroll
            for (int j = 0; j < 4; j++) {
                int n = n0 + tx * TN + jj + j;
                float v = acc[i][jj + j];
                if (bias) v += bias[n];
                if (RELU) v = fmaxf(v, 0.f);
                po[j] = v;
            }
            *reinterpret_cast<float4*>(&C[(long long)m * ldc + (n0 + tx * TN + jj)]) = o;
        }
    }
}

// ---------------- block reductions (256 threads = 8 warps) ----------------
__device__ __forceinline__ float block_sum(float v, float* sh) {
    #pragma unroll
    for (int o = 16; o; o >>= 1) v += __shfl_xor_sync(0xffffffffu, v, o);
    __syncthreads();
    if ((threadIdx.x & 31) == 0) sh[threadIdx.x >> 5] = v;
    __syncthreads();
    float r = sh[0];
    #pragma unroll
    for (int i = 1; i < 8; i++) r += sh[i];
    return r;
}

__device__ __forceinline__ float block_max(float v, float* sh) {
    #pragma unroll
    for (int o = 16; o; o >>= 1) v = fmaxf(v, __shfl_xor_sync(0xffffffffu, v, o));
    __syncthreads();
    if ((threadIdx.x & 31) == 0) sh[threadIdx.x >> 5] = v;
    __syncthreads();
    float r = sh[0];
    #pragma unroll
    for (int i = 1; i < 8; i++) r = fmaxf(r, sh[i]);
    return r;
}

// ---------------- fused: per-head softmax -> head mean -> causal mask
//                  -> +pos bias -> second softmax ----------------
// grid (L, B), block 256; each thread owns 4 keys (k = tid*4+j)
__global__ void __launch_bounds__(256)
attn_merge_kernel(const float* __restrict__ logits, float* __restrict__ Wout)
{
    __shared__ float sh[8];
    const int q   = blockIdx.x;
    const int b   = blockIdx.y;
    const int tid = threadIdx.x;

    float acc[4] = {0.f, 0.f, 0.f, 0.f};

    for (int h = 0; h < HH; h++) {
        const float4* row = reinterpret_cast<const float4*>(
            logits + (((long long)(b * HH + h)) * LL_ + q) * LL_);
        float4 rv = row[tid];
        float v[4] = {rv.x * 0.125f, rv.y * 0.125f, rv.z * 0.125f, rv.w * 0.125f};
        float m = fmaxf(fmaxf(v[0], v[1]), fmaxf(v[2], v[3]));
        m = block_max(m, sh);
        float e[4], ls = 0.f;
        #pragma unroll
        for (int j = 0; j < 4; j++) { e[j] = expf(v[j] - m); ls += e[j]; }
        float s = block_sum(ls, sh);
        float inv = 1.f / s;
        #pragma unroll
        for (int j = 0; j < 4; j++) acc[j] += e[j] * inv;
    }

    // head mean, causal mask, + exp(-|q-k|*0.1) positional bias
    float pv[4];
    #pragma unroll
    for (int j = 0; j < 4; j++) {
        int k = tid * 4 + j;
        float a = acc[j] * 0.125f;  // mean over 8 heads
        float p = expf(-fabsf((float)(q - k)) * 0.1f);
        pv[j] = (k > q) ? -INFINITY : (a + p);
    }
    float m = fmaxf(fmaxf(pv[0], pv[1]), fmaxf(pv[2], pv[3]));
    m = block_max(m, sh);
    float e[4], ls = 0.f;
    #pragma unroll
    for (int j = 0; j < 4; j++) { e[j] = expf(pv[j] - m); ls += e[j]; }
    float s = block_sum(ls, sh);
    float inv = 1.f / s;

    float4 o = {e[0] * inv, e[1] * inv, e[2] * inv, e[3] * inv};
    reinterpret_cast<float4*>(Wout + ((long long)b * LL_ + q) * LL_)[tid] = o;
}

// ---------------- fused residual + LN (+ optional second LN) ----------------
// grid 8192, block 256; 2 elems/thread (E=512)
__global__ void __launch_bounds__(256)
ln_dual_kernel(const float* __restrict__ xin, const float* __restrict__ res,
               const float* __restrict__ g1, const float* __restrict__ b1,
               const float* __restrict__ g2, const float* __restrict__ b2,
               float* __restrict__ xout)
{
    __shared__ float sh[8];
    const long long row = blockIdx.x;
    const int t = threadIdx.x;
    const long long base = row * EE;

    float v0 = xin[base + t]       + res[base + t];
    float v1 = xin[base + 256 + t] + res[base + 256 + t];

    float mean = block_sum(v0 + v1, sh) * (1.f / EE);
    float d0 = v0 - mean, d1 = v1 - mean;
    float var = block_sum(d0 * d0 + d1 * d1, sh) * (1.f / EE);
    float r = rsqrtf(var + 1e-5f);
    float y0 = d0 * r * g1[t] + b1[t];
    float y1 = d1 * r * g1[256 + t] + b1[256 + t];

    mean = block_sum(y0 + y1, sh) * (1.f / EE);
    d0 = y0 - mean; d1 = y1 - mean;
    var = block_sum(d0 * d0 + d1 * d1, sh) * (1.f / EE);
    r = rsqrtf(var + 1e-5f);
    xout[base + t]       = d0 * r * g2[t] + b2[t];
    xout[base + 256 + t] = d1 * r * g2[256 + t] + b2[256 + t];
}

__global__ void __launch_bounds__(256)
ln_single_kernel(const float* __restrict__ xin, const float* __restrict__ res,
                 const float* __restrict__ g, const float* __restrict__ b,
                 float* __restrict__ xout)
{
    __shared__ float sh[8];
    const long long row = blockIdx.x;
    const int t = threadIdx.x;
    const long long base = row * EE;

    float v0 = xin[base + t]       + res[base + t];
    float v1 = xin[base + 256 + t] + res[base + 256 + t];

    float mean = block_sum(v0 + v1, sh) * (1.f / EE);
    float d0 = v0 - mean, d1 = v1 - mean;
    float var = block_sum(d0 * d0 + d1 * d1, sh) * (1.f / EE);
    float r = rsqrtf(var + 1e-5f);
    xout[base + t]       = d0 * r * g[t] + b[t];
    xout[base + 256 + t] = d1 * r * g[256 + t] + b[256 + t];
}

// ---------------- host orchestration ----------------
extern "C" void kernel_launch(void* const* d_in, const int* in_sizes, int n_in,
                              void* d_out, int out_size)
{
    const float* x_in = (const float*)d_in[0];
    const float* Wqkv = (const float*)d_in[1];
    const float* bqkv = (const float*)d_in[2];
    const float* W1   = (const float*)d_in[3];
    const float* b1   = (const float*)d_in[4];
    const float* W2   = (const float*)d_in[5];
    const float* b2   = (const float*)d_in[6];
    const float* g1   = (const float*)d_in[7];
    const float* bt1  = (const float*)d_in[8];
    const float* g2   = (const float*)d_in[9];
    const float* bt2  = (const float*)d_in[10];
    const float* g3   = (const float*)d_in[11];
    const float* bt3  = (const float*)d_in[12];

    float *px, *pqkv, *plog, *pW, *psa, *ph;
    cudaGetSymbolAddress((void**)&px,   g_x);
    cudaGetSymbolAddress((void**)&pqkv, g_qkv);
    cudaGetSymbolAddress((void**)&plog, g_log);
    cudaGetSymbolAddress((void**)&pW,   g_W);
    cudaGetSymbolAddress((void**)&psa,  g_sa);
    cudaGetSymbolAddress((void**)&ph,   g_h);

    const long long LE   = (long long)LL_ * EE;        // 1024*512
    const long long LQ   = (long long)LL_ * 3 * EE;    // 1024*1536 (qkv batch stride)
    const long long LLs  = (long long)LL_ * LL_;       // 1024*1024

    for (int d = 0; d < DEPTH_; d++) {
        const float* x = (d == 0) ? x_in : px;

        // 1) qkv = x @ Wqkv[d]^T + bqkv[d]   (M=8192, N=1536, K=512)
        sgemm_kernel<true, false><<<dim3(1536 / BN, MM / BM, 1), 256>>>(
            x, EE, 0, 0,
            Wqkv + (size_t)d * 3 * EE * EE, EE, 0, 0,
            pqkv, 3 * EE, 0, 0,
            bqkv + (size_t)d * 3 * EE,
            MM, 3 * EE, EE, 1);

        // 2) per-(b,h) logits = q @ k^T   (M=N=1024, K=64), z = b*8+h
        sgemm_kernel<true, false><<<dim3(LL_ / BN, LL_ / BM, Bb * HH), 256>>>(
            pqkv,       3 * EE, HD, LQ,           // +h*64, +b*L*1536
            pqkv + EE,  3 * EE, HD, LQ,           // k part (offset E)
            plog, LL_, LLs, (long long)HH * LLs,  // z*L*L
            nullptr,
            LL_, LL_, HD, HH);

        // 3) fused softmax / mean / mask / pos / softmax -> W [B,L,L]
        attn_merge_kernel<<<dim3(LL_, Bb), 256>>>(plog, pW);

        // 4) sa[b] = W[b] @ x[b]   (per-batch M=1024, N=512, K=1024)
        sgemm_kernel<false, false><<<dim3(EE / BN, LL_ / BM, Bb), 256>>>(
            pW, LL_, LLs, 0,
            x,  EE,  LE,  0,
            psa, EE, LE,  0,
            nullptr,
            LL_, EE, LL_, Bb);

        // 5) x = LN2(LN1(x + sa))
        ln_dual_kernel<<<MM, 256>>>(x, psa,
                                    g1 + d * EE, bt1 + d * EE,
                                    g2 + d * EE, bt2 + d * EE, px);

        // 6) h = relu(x @ W1[d]^T + b1[d])   (8192, 2048, 512)
        sgemm_kernel<true, true><<<dim3(FFD / BN, MM / BM, 1), 256>>>(
            px, EE, 0, 0,
            W1 + (size_t)d * FFD * EE, EE, 0, 0,
            ph, FFD, 0, 0,
            b1 + (size_t)d * FFD,
            MM, FFD, EE, 1);

        // 7) ff = h @ W2[d]^T + b2[d]   (8192, 512, 2048)
        sgemm_kernel<true, false><<<dim3(EE / BN, MM / BM, 1), 256>>>(
            ph, FFD, 0, 0,
            W2 + (size_t)d * EE * FFD, FFD, 0, 0,
            psa, EE, 0, 0,
            b2 + (size_t)d * EE,
            MM, EE, FFD, 1);

        // 8) x = LN3(x + ff)  (final layer writes straight to d_out)
        float* xo = (d == DEPTH_ - 1) ? (float*)d_out : px;
        ln_single_kernel<<<MM, 256>>>(px, psa, g3 + d * EE, bt3 + d * EE, xo);
    }
}

// round 8
// speedup vs baseline: 1.0822x; 1.0822x over previous
#include <cuda_runtime.h>
#include <math.h>

// ---------------- problem constants ----------------
#define Bb 8
#define LL_ 1024
#define EE 512
#define HH 8
#define HD 64
#define FFD 2048
#define DEPTH_ 4
#define MM (Bb*LL_)   // 8192

// ---------------- device scratch (no allocations allowed) ----------------
__device__ float g_x   [(size_t)MM * EE];          // 16 MB  activations
__device__ float g_qkv [(size_t)MM * 3 * EE];      // 48 MB
__device__ float g_log [(size_t)Bb * HH * LL_ * LL_]; // 256 MB per-head logits
__device__ float g_W   [(size_t)Bb * LL_ * LL_];   // 32 MB  attention weights
__device__ float g_sa  [(size_t)MM * EE];          // 16 MB  attn out / ffn out
__device__ float g_h   [(size_t)MM * FFD];         // 64 MB  ffn hidden

// ---------------- generic SGEMM: C[M,N] = A[M,K] @ op(B) + bias ----------------
// BT=true : B is [N,K] row-major (weights, K contiguous)
// BT=false: B is [K,N] row-major (N contiguous)
// z-batch: zi = z % zmod, zo = z / zmod; ptr += zi*zs + zo*zs2
// Double-buffered smem + software-pipelined fragments.
#define BM 128
#define BN 128
#define BK 8
#define TM 8
#define TN 8

template<bool BT, bool RELU>
__global__ void __launch_bounds__(256, 2)
sgemm_kernel(const float* __restrict__ A, int lda, long long zsa, long long zsa2,
             const float* __restrict__ Bm, int ldb, long long zsb, long long zsb2,
             float* __restrict__ C, int ldc, long long zsc, long long zsc2,
             const float* __restrict__ bias,
             int M, int N, int K, int zmod)
{
    int z  = blockIdx.z;
    int zi = z % zmod;
    int zo = z / zmod;
    A  += (long long)zi * zsa + (long long)zo * zsa2;
    Bm += (long long)zi * zsb + (long long)zo * zsb2;
    C  += (long long)zi * zsc + (long long)zo * zsc2;

    __shared__ float As[2][BK][BM];
    __shared__ float Bs[2][BK][BN];

    const int tid = threadIdx.x;
    const int tx  = tid & 15;
    const int ty  = tid >> 4;
    const int m0  = blockIdx.y * BM;
    const int n0  = blockIdx.x * BN;

    const int arow = tid >> 1;        // 0..127
    const int acol = (tid & 1) * 4;   // 0 or 4
    const int brow = tid >> 5;        // 0..7   (BT=false path)
    const int bcol = (tid & 31) * 4;  // 0..124 (BT=false path)

    float acc[TM][TN];
    #pragma unroll
    for (int i = 0; i < TM; i++)
        #pragma unroll
        for (int j = 0; j < TN; j++) acc[i][j] = 0.f;

    // ---- prologue: load first tile into buffer 0 ----
    {
        float4 av = *reinterpret_cast<const float4*>(
            &A[(long long)(m0 + arow) * lda + acol]);
        As[0][acol + 0][arow] = av.x;
        As[0][acol + 1][arow] = av.y;
        As[0][acol + 2][arow] = av.z;
        As[0][acol + 3][arow] = av.w;
        if (BT) {
            float4 bv = *reinterpret_cast<const float4*>(
                &Bm[(long long)(n0 + arow) * ldb + acol]);
            Bs[0][acol + 0][arow] = bv.x;
            Bs[0][acol + 1][arow] = bv.y;
            Bs[0][acol + 2][arow] = bv.z;
            Bs[0][acol + 3][arow] = bv.w;
        } else {
            float4 bv = *reinterpret_cast<const float4*>(
                &Bm[(long long)brow * ldb + (n0 + bcol)]);
            *reinterpret_cast<float4*>(&Bs[0][brow][bcol]) = bv;
        }
    }
    __syncthreads();

    int buf = 0;
    for (int k0 = 0; k0 < K; k0 += BK) {
        const bool has_next = (k0 + BK) < K;

        // ---- prefetch next tile from global into registers ----
        float4 av2, bv2;
        if (has_next) {
            av2 = *reinterpret_cast<const float4*>(
                &A[(long long)(m0 + arow) * lda + (k0 + BK + acol)]);
            if (BT) {
                bv2 = *reinterpret_cast<const float4*>(
                    &Bm[(long long)(n0 + arow) * ldb + (k0 + BK + acol)]);
            } else {
                bv2 = *reinterpret_cast<const float4*>(
                    &Bm[(long long)(k0 + BK + brow) * ldb + (n0 + bcol)]);
            }
        }

        // ---- compute from smem[buf], software-pipelined fragments ----
        float af[2][TM], bf[2][TN];
        #pragma unroll
        for (int i = 0; i < TM; i++) af[0][i] = As[buf][0][ty * TM + i];
        #pragma unroll
        for (int j = 0; j < TN; j++) bf[0][j] = Bs[buf][0][tx * TN + j];

        #pragma unroll
        for (int kk = 0; kk < BK; kk++) {
            int cur = kk & 1;
            if (kk < BK - 1) {
                int nxt = cur ^ 1;
                #pragma unroll
                for (int i = 0; i < TM; i++) af[nxt][i] = As[buf][kk + 1][ty * TM + i];
                #pragma unroll
                for (int j = 0; j < TN; j++) bf[nxt][j] = Bs[buf][kk + 1][tx * TN + j];
            }
            #pragma unroll
            for (int i = 0; i < TM; i++)
                #pragma unroll
                for (int j = 0; j < TN; j++)
                    acc[i][j] += af[cur][i] * bf[cur][j];
        }

        // ---- store prefetched tile into the other buffer ----
        if (has_next) {
            int nb = buf ^ 1;
            As[nb][acol + 0][arow] = av2.x;
            As[nb][acol + 1][arow] = av2.y;
            As[nb][acol + 2][arow] = av2.z;
            As[nb][acol + 3][arow] = av2.w;
            if (BT) {
                Bs[nb][acol + 0][arow] = bv2.x;
                Bs[nb][acol + 1][arow] = bv2.y;
                Bs[nb][acol + 2][arow] = bv2.z;
                Bs[nb][acol + 3][arow] = bv2.w;
            } else {
                *reinterpret_cast<float4*>(&Bs[nb][brow][bcol]) = bv2;
            }
            __syncthreads();
            buf = nb;
        }
    }

    #pragma unroll
    for (int i = 0; i < TM; i++) {
        int m = m0 + ty * TM + i;
        #pragma unroll
        for (int jj = 0; jj < TN; jj += 4) {
            float4 o;
            float* po = &o.x;
            #pragma unroll
            for (int j = 0; j < 4; j++) {
                int n = n0 + tx * TN + jj + j;
                float v = acc[i][jj + j];
                if (bias) v += bias[n];
                if (RELU) v = fmaxf(v, 0.f);
                po[j] = v;
            }
            *reinterpret_cast<float4*>(&C[(long long)m * ldc + (n0 + tx * TN + jj)]) = o;
        }
    }
}

// ---------------- block reductions (256 threads = 8 warps) ----------------
__device__ __forceinline__ float block_sum(float v, float* sh) {
    #pragma unroll
    for (int o = 16; o; o >>= 1) v += __shfl_xor_sync(0xffffffffu, v, o);
    __syncthreads();
    if ((threadIdx.x & 31) == 0) sh[threadIdx.x >> 5] = v;
    __syncthreads();
    float r = sh[0];
    #pragma unroll
    for (int i = 1; i < 8; i++) r += sh[i];
    return r;
}

__device__ __forceinline__ float block_max(float v, float* sh) {
    #pragma unroll
    for (int o = 16; o; o >>= 1) v = fmaxf(v, __shfl_xor_sync(0xffffffffu, v, o));
    __syncthreads();
    if ((threadIdx.x & 31) == 0) sh[threadIdx.x >> 5] = v;
    __syncthreads();
    float r = sh[0];
    #pragma unroll
    for (int i = 1; i < 8; i++) r = fmaxf(r, sh[i]);
    return r;
}

// ---------------- fused: per-head softmax -> head mean -> causal mask
//                  -> +pos bias -> second softmax ----------------
// grid (L, B), block 256; each thread owns 4 keys (k = tid*4+j)
__global__ void __launch_bounds__(256)
attn_merge_kernel(const float* __restrict__ logits, float* __restrict__ Wout)
{
    __shared__ float sh[8];
    const int q   = blockIdx.x;
    const int b   = blockIdx.y;
    const int tid = threadIdx.x;

    float acc[4] = {0.f, 0.f, 0.f, 0.f};

    for (int h = 0; h < HH; h++) {
        const float4* row = reinterpret_cast<const float4*>(
            logits + (((long long)(b * HH + h)) * LL_ + q) * LL_);
        float4 rv = row[tid];
        float v[4] = {rv.x * 0.125f, rv.y * 0.125f, rv.z * 0.125f, rv.w * 0.125f};
        float m = fmaxf(fmaxf(v[0], v[1]), fmaxf(v[2], v[3]));
        m = block_max(m, sh);
        float e[4], ls = 0.f;
        #pragma unroll
        for (int j = 0; j < 4; j++) { e[j] = expf(v[j] - m); ls += e[j]; }
        float s = block_sum(ls, sh);
        float inv = 1.f / s;
        #pragma unroll
        for (int j = 0; j < 4; j++) acc[j] += e[j] * inv;
    }

    // head mean, causal mask, + exp(-|q-k|*0.1) positional bias
    float pv[4];
    #pragma unroll
    for (int j = 0; j < 4; j++) {
        int k = tid * 4 + j;
        float a = acc[j] * 0.125f;  // mean over 8 heads
        float p = expf(-fabsf((float)(q - k)) * 0.1f);
        pv[j] = (k > q) ? -INFINITY : (a + p);
    }
    float m = fmaxf(fmaxf(pv[0], pv[1]), fmaxf(pv[2], pv[3]));
    m = block_max(m, sh);
    float e[4], ls = 0.f;
    #pragma unroll
    for (int j = 0; j < 4; j++) { e[j] = expf(pv[j] - m); ls += e[j]; }
    float s = block_sum(ls, sh);
    float inv = 1.f / s;

    float4 o = {e[0] * inv, e[1] * inv, e[2] * inv, e[3] * inv};
    reinterpret_cast<float4*>(Wout + ((long long)b * LL_ + q) * LL_)[tid] = o;
}

// ---------------- fused residual + LN (+ optional second LN) ----------------
// grid 8192, block 256; 2 elems/thread (E=512)
__global__ void __launch_bounds__(256)
ln_dual_kernel(const float* __restrict__ xin, const float* __restrict__ res,
               const float* __restrict__ g1, const float* __restrict__ b1,
               const float* __restrict__ g2, const float* __restrict__ b2,
               float* __restrict__ xout)
{
    __shared__ float sh[8];
    const long long row = blockIdx.x;
    const int t = threadIdx.x;
    const long long base = row * EE;

    float v0 = xin[base + t]       + res[base + t];
    float v1 = xin[base + 256 + t] + res[base + 256 + t];

    float mean = block_sum(v0 + v1, sh) * (1.f / EE);
    float d0 = v0 - mean, d1 = v1 - mean;
    float var = block_sum(d0 * d0 + d1 * d1, sh) * (1.f / EE);
    float r = rsqrtf(var + 1e-5f);
    float y0 = d0 * r * g1[t] + b1[t];
    float y1 = d1 * r * g1[256 + t] + b1[256 + t];

    mean = block_sum(y0 + y1, sh) * (1.f / EE);
    d0 = y0 - mean; d1 = y1 - mean;
    var = block_sum(d0 * d0 + d1 * d1, sh) * (1.f / EE);
    r = rsqrtf(var + 1e-5f);
    xout[base + t]       = d0 * r * g2[t] + b2[t];
    xout[base + 256 + t] = d1 * r * g2[256 + t] + b2[256 + t];
}

__global__ void __launch_bounds__(256)
ln_single_kernel(const float* __restrict__ xin, const float* __restrict__ res,
                 const float* __restrict__ g, const float* __restrict__ b,
                 float* __restrict__ xout)
{
    __shared__ float sh[8];
    const long long row = blockIdx.x;
    const int t = threadIdx.x;
    const long long base = row * EE;

    float v0 = xin[base + t]       + res[base + t];
    float v1 = xin[base + 256 + t] + res[base + 256 + t];

    float mean = block_sum(v0 + v1, sh) * (1.f / EE);
    float d0 = v0 - mean, d1 = v1 - mean;
    float var = block_sum(d0 * d0 + d1 * d1, sh) * (1.f / EE);
    float r = rsqrtf(var + 1e-5f);
    xout[base + t]       = d0 * r * g[t] + b[t];
    xout[base + 256 + t] = d1 * r * g[256 + t] + b[256 + t];
}

// ---------------- host orchestration ----------------
extern "C" void kernel_launch(void* const* d_in, const int* in_sizes, int n_in,
                              void* d_out, int out_size)
{
    const float* x_in = (const float*)d_in[0];
    const float* Wqkv = (const float*)d_in[1];
    const float* bqkv = (const float*)d_in[2];
    const float* W1   = (const float*)d_in[3];
    const float* b1   = (const float*)d_in[4];
    const float* W2   = (const float*)d_in[5];
    const float* b2   = (const float*)d_in[6];
    const float* g1   = (const float*)d_in[7];
    const float* bt1  = (const float*)d_in[8];
    const float* g2   = (const float*)d_in[9];
    const float* bt2  = (const float*)d_in[10];
    const float* g3   = (const float*)d_in[11];
    const float* bt3  = (const float*)d_in[12];

    float *px, *pqkv, *plog, *pW, *psa, *ph;
    cudaGetSymbolAddress((void**)&px,   g_x);
    cudaGetSymbolAddress((void**)&pqkv, g_qkv);
    cudaGetSymbolAddress((void**)&plog, g_log);
    cudaGetSymbolAddress((void**)&pW,   g_W);
    cudaGetSymbolAddress((void**)&psa,  g_sa);
    cudaGetSymbolAddress((void**)&ph,   g_h);

    const long long LE   = (long long)LL_ * EE;        // 1024*512
    const long long LQ   = (long long)LL_ * 3 * EE;    // 1024*1536 (qkv batch stride)
    const long long LLs  = (long long)LL_ * LL_;       // 1024*1024

    for (int d = 0; d < DEPTH_; d++) {
        const float* x = (d == 0) ? x_in : px;

        // 1) qkv = x @ Wqkv[d]^T + bqkv[d]   (M=8192, N=1536, K=512)
        sgemm_kernel<true, false><<<dim3(1536 / BN, MM / BM, 1), 256>>>(
            x, EE, 0, 0,
            Wqkv + (size_t)d * 3 * EE * EE, EE, 0, 0,
            pqkv, 3 * EE, 0, 0,
            bqkv + (size_t)d * 3 * EE,
            MM, 3 * EE, EE, 1);

        // 2) per-(b,h) logits = q @ k^T   (M=N=1024, K=64), z = b*8+h
        sgemm_kernel<true, false><<<dim3(LL_ / BN, LL_ / BM, Bb * HH), 256>>>(
            pqkv,       3 * EE, HD, LQ,           // +h*64, +b*L*1536
            pqkv + EE,  3 * EE, HD, LQ,           // k part (offset E)
            plog, LL_, LLs, (long long)HH * LLs,  // z*L*L
            nullptr,
            LL_, LL_, HD, HH);

        // 3) fused softmax / mean / mask / pos / softmax -> W [B,L,L]
        attn_merge_kernel<<<dim3(LL_, Bb), 256>>>(plog, pW);

        // 4) sa[b] = W[b] @ x[b]   (per-batch M=1024, N=512, K=1024)
        sgemm_kernel<false, false><<<dim3(EE / BN, LL_ / BM, Bb), 256>>>(
            pW, LL_, LLs, 0,
            x,  EE,  LE,  0,
            psa, EE, LE,  0,
            nullptr,
            LL_, EE, LL_, Bb);

        // 5) x = LN2(LN1(x + sa))
        ln_dual_kernel<<<MM, 256>>>(x, psa,
                                    g1 + d * EE, bt1 + d * EE,
                                    g2 + d * EE, bt2 + d * EE, px);

        // 6) h = relu(x @ W1[d]^T + b1[d])   (8192, 2048, 512)
        sgemm_kernel<true, true><<<dim3(FFD / BN, MM / BM, 1), 256>>>(
            px, EE, 0, 0,
            W1 + (size_t)d * FFD * EE, EE, 0, 0,
            ph, FFD, 0, 0,
            b1 + (size_t)d * FFD,
            MM, FFD, EE, 1);

        // 7) ff = h @ W2[d]^T + b2[d]   (8192, 512, 2048)
        sgemm_kernel<true, false><<<dim3(EE / BN, MM / BM, 1), 256>>>(
            ph, FFD, 0, 0,
            W2 + (size_t)d * EE * FFD, FFD, 0, 0,
            psa, EE, 0, 0,
            b2 + (size_t)d * EE,
            MM, EE, FFD, 1);

        // 8) x = LN3(x + ff)  (final layer writes straight to d_out)
        float* xo = (d == DEPTH_ - 1) ? (float*)d_out : px;
        ln_single_kernel<<<MM, 256>>>(px, psa, g3 + d * EE, bt3 + d * EE, xo);
    }
}